// round 3
// baseline (speedup 1.0000x reference)
#include <cuda_runtime.h>
#include <cuda_bf16.h>
#include <cstdint>

// Problem dims (fixed by the reference)
#define BATCH   8
#define LSEQ    2048
#define DMODEL  768
#define DIN     1536
#define NHEADS  4
#define DHEAD   192
#define MROWS   (BATCH * LSEQ)   // 16384

// ---------------------------------------------------------------------------
// Scratch (allocation-free rule: __device__ globals)
// ---------------------------------------------------------------------------
__device__ float g_Q[MROWS * DMODEL];
__device__ float g_K[MROWS * DMODEL];
__device__ float g_V[MROWS * DMODEL];
__device__ float g_Ctx[MROWS * DMODEL];

// ---------------------------------------------------------------------------
// SGEMM: C[M,N] = A[M,K] @ B[K,N] + bias[N]
// 128x128 tile, BK=8, 8x8 per thread, 256 threads.
// Requires M%128==0, N%128==0, K%8==0 (true for all our shapes).
// ---------------------------------------------------------------------------
#define GBM 128
#define GBN 128
#define GBK 8
#define GTM 8
#define GTN 8

__global__ __launch_bounds__(256, 2)
void sgemm_bias(const float* __restrict__ A, const float* __restrict__ B,
                const float* __restrict__ bias, float* __restrict__ C,
                int M, int N, int K) {
    __shared__ float As[GBK][GBM];
    __shared__ float Bs[GBK][GBN];

    const int bx = blockIdx.x;   // N tile
    const int by = blockIdx.y;   // M tile
    const int tid = threadIdx.x;
    const int tx = tid & 15;     // 0..15
    const int ty = tid >> 4;     // 0..15

    const float* Ab = A + (size_t)by * GBM * K;
    const float* Bb = B + (size_t)bx * GBN;

    const int aRow = tid >> 1;         // 0..127
    const int aCol = (tid & 1) * 4;    // 0 or 4
    const int bRow = tid >> 5;         // 0..7
    const int bCol = (tid & 31) * 4;   // 0..124

    float acc[GTM][GTN];
#pragma unroll
    for (int i = 0; i < GTM; i++)
#pragma unroll
        for (int j = 0; j < GTN; j++) acc[i][j] = 0.f;

    for (int k0 = 0; k0 < K; k0 += GBK) {
        float4 a4 = *(const float4*)(Ab + (size_t)aRow * K + k0 + aCol);
        As[aCol + 0][aRow] = a4.x;
        As[aCol + 1][aRow] = a4.y;
        As[aCol + 2][aRow] = a4.z;
        As[aCol + 3][aRow] = a4.w;
        float4 b4 = *(const float4*)(Bb + (size_t)(k0 + bRow) * N + bCol);
        *(float4*)&Bs[bRow][bCol] = b4;
        __syncthreads();

#pragma unroll
        for (int k = 0; k < GBK; k++) {
            float ar[GTM], br[GTN];
#pragma unroll
            for (int i = 0; i < GTM; i++) ar[i] = As[k][ty * GTM + i];
#pragma unroll
            for (int j = 0; j < GTN; j++) br[j] = Bs[k][tx * GTN + j];
#pragma unroll
            for (int i = 0; i < GTM; i++)
#pragma unroll
                for (int j = 0; j < GTN; j++) acc[i][j] += ar[i] * br[j];
        }
        __syncthreads();
    }

#pragma unroll
    for (int i = 0; i < GTM; i++) {
        const int row = by * GBM + ty * GTM + i;
#pragma unroll
        for (int j = 0; j < GTN; j += 4) {
            const int col = bx * GBN + tx * GTN + j;
            float4 o;
            o.x = acc[i][j + 0] + bias[col + 0];
            o.y = acc[i][j + 1] + bias[col + 1];
            o.z = acc[i][j + 2] + bias[col + 2];
            o.w = acc[i][j + 3] + bias[col + 3];
            *(float4*)(C + (size_t)row * N + col) = o;
        }
    }
}

// ---------------------------------------------------------------------------
// Flash attention (fp32, unscaled logits, online softmax).
// Grid: (LSEQ/BQ, BATCH*NHEADS). 256 threads.
// Q,K stored d-major in smem (conflict-free score phase). V row-major.
// Thread layout: rg = tid>>4 -> 4 q-rows (rg*4..+3); tid&15 -> kk / d-chunk.
// O per thread: 4 rows x 12 dims = 48 regs.
// ---------------------------------------------------------------------------
#define BQ  64
#define BS  32
#define QST 65    // Qst[d][r] stride
#define KST 33    // Kst[d][kk] stride
#define VST 196   // Vs[kk][d] stride
#define SST 33    // Ss[r][kk] stride

#define ATTN_SMEM_FLOATS (DHEAD*QST + DHEAD*KST + BS*VST + BQ*SST + 3*BQ)
#define ATTN_SMEM_BYTES  (ATTN_SMEM_FLOATS * 4)

__global__ __launch_bounds__(256, 2)
void attn_kernel(const float* __restrict__ Q, const float* __restrict__ K,
                 const float* __restrict__ V, float* __restrict__ Ctx) {
    extern __shared__ float sm[];
    float* Qst    = sm;                       // DHEAD*QST
    float* Kst    = Qst + DHEAD * QST;        // DHEAD*KST
    float* Vs     = Kst + DHEAD * KST;        // BS*VST
    float* Ss     = Vs + BS * VST;            // BQ*SST
    float* ms     = Ss + BQ * SST;            // BQ
    float* ls     = ms + BQ;                  // BQ
    float* alphas = ls + BQ;                  // BQ

    const int tid   = threadIdx.x;
    const int qtile = blockIdx.x;
    const int bh    = blockIdx.y;
    const int b     = bh / NHEADS;
    const int h     = bh % NHEADS;

    const float* Qg = Q + (size_t)b * LSEQ * DMODEL + h * DHEAD;
    const float* Kg = K + (size_t)b * LSEQ * DMODEL + h * DHEAD;
    const float* Vg = V + (size_t)b * LSEQ * DMODEL + h * DHEAD;

    // Load Q tile transposed: Qst[d][r]
    for (int i = tid; i < BQ * 48; i += 256) {
        const int r  = i / 48;
        const int dc = (i % 48) * 4;
        float4 q4 = *(const float4*)(Qg + (size_t)(qtile * BQ + r) * DMODEL + dc);
        Qst[(dc + 0) * QST + r] = q4.x;
        Qst[(dc + 1) * QST + r] = q4.y;
        Qst[(dc + 2) * QST + r] = q4.z;
        Qst[(dc + 3) * QST + r] = q4.w;
    }
    if (tid < BQ) { ms[tid] = -1e30f; ls[tid] = 0.f; }

    const int rg  = tid >> 4;          // 0..15
    const int r0  = rg * 4;            // row group base
    const int kk0 = tid & 15;          // score column base (and +16)
    const int dc0 = (tid & 15) * 12;   // output dim base (12 dims)

    float O[48];
#pragma unroll
    for (int i = 0; i < 48; i++) O[i] = 0.f;

    for (int t = 0; t < LSEQ / BS; t++) {
        __syncthreads();   // previous iteration's readers done

        // Load K tile (transposed) + V tile
        for (int i = tid; i < BS * 48; i += 256) {
            const int kr = i / 48;
            const int dc = (i % 48) * 4;
            float4 k4 = *(const float4*)(Kg + (size_t)(t * BS + kr) * DMODEL + dc);
            Kst[(dc + 0) * KST + kr] = k4.x;
            Kst[(dc + 1) * KST + kr] = k4.y;
            Kst[(dc + 2) * KST + kr] = k4.z;
            Kst[(dc + 3) * KST + kr] = k4.w;
            float4 v4 = *(const float4*)(Vg + (size_t)(t * BS + kr) * DMODEL + dc);
            *(float4*)(Vs + kr * VST + dc) = v4;
        }
        __syncthreads();

        // Scores: rows r0..r0+3 x columns {kk0, kk0+16}
        float acc[4][2];
#pragma unroll
        for (int i = 0; i < 4; i++) { acc[i][0] = 0.f; acc[i][1] = 0.f; }
#pragma unroll 4
        for (int d = 0; d < DHEAD; d++) {
            const float kv0 = Kst[d * KST + kk0];
            const float kv1 = Kst[d * KST + kk0 + 16];
#pragma unroll
            for (int i = 0; i < 4; i++) {
                const float qv = Qst[d * QST + r0 + i];
                acc[i][0] += qv * kv0;
                acc[i][1] += qv * kv1;
            }
        }
#pragma unroll
        for (int i = 0; i < 4; i++) {
            Ss[(r0 + i) * SST + kk0]      = acc[i][0];
            Ss[(r0 + i) * SST + kk0 + 16] = acc[i][1];
        }
        __syncthreads();

        // Row max + alpha (one thread per row)
        if (tid < BQ) {
            const float m_old = ms[tid];
            float tmax = m_old;
#pragma unroll
            for (int k = 0; k < BS; k++) tmax = fmaxf(tmax, Ss[tid * SST + k]);
            ms[tid] = tmax;
            alphas[tid] = __expf(m_old - tmax);
        }
        __syncthreads();

        // Exponentiate in place (same mapping as score phase)
#pragma unroll
        for (int i = 0; i < 4; i++) {
            const float mrow = ms[r0 + i];
            Ss[(r0 + i) * SST + kk0]      = __expf(acc[i][0] - mrow);
            Ss[(r0 + i) * SST + kk0 + 16] = __expf(acc[i][1] - mrow);
        }
        __syncthreads();

        // l update (row threads) runs concurrently with PV (reads only)
        if (tid < BQ) {
            float s = 0.f;
#pragma unroll
            for (int k = 0; k < BS; k++) s += Ss[tid * SST + k];
            ls[tid] = ls[tid] * alphas[tid] + s;
        }

        // PV: rescale O then accumulate P @ V
        float al[4];
#pragma unroll
        for (int i = 0; i < 4; i++) al[i] = alphas[r0 + i];
#pragma unroll
        for (int i = 0; i < 4; i++)
#pragma unroll
            for (int j = 0; j < 12; j++) O[i * 12 + j] *= al[i];

#pragma unroll 2
        for (int k = 0; k < BS; k++) {
            float p[4];
#pragma unroll
            for (int i = 0; i < 4; i++) p[i] = Ss[(r0 + i) * SST + k];
            const float4 v0 = *(const float4*)(Vs + k * VST + dc0);
            const float4 v1 = *(const float4*)(Vs + k * VST + dc0 + 4);
            const float4 v2 = *(const float4*)(Vs + k * VST + dc0 + 8);
#pragma unroll
            for (int i = 0; i < 4; i++) {
                O[i * 12 + 0]  += p[i] * v0.x;
                O[i * 12 + 1]  += p[i] * v0.y;
                O[i * 12 + 2]  += p[i] * v0.z;
                O[i * 12 + 3]  += p[i] * v0.w;
                O[i * 12 + 4]  += p[i] * v1.x;
                O[i * 12 + 5]  += p[i] * v1.y;
                O[i * 12 + 6]  += p[i] * v1.z;
                O[i * 12 + 7]  += p[i] * v1.w;
                O[i * 12 + 8]  += p[i] * v2.x;
                O[i * 12 + 9]  += p[i] * v2.y;
                O[i * 12 + 10] += p[i] * v2.z;
                O[i * 12 + 11] += p[i] * v2.w;
            }
        }
    }
    __syncthreads();   // ls final values visible

    // Normalize + write ctx (layout [B, L, H*DHEAD] = [16384, 768])
#pragma unroll
    for (int i = 0; i < 4; i++) {
        const float inv = 1.f / ls[r0 + i];
        const int row = qtile * BQ + r0 + i;
        float* dst = Ctx + ((size_t)b * LSEQ + row) * DMODEL + h * DHEAD + dc0;
#pragma unroll
        for (int j = 0; j < 3; j++) {
            float4 o;
            o.x = O[i * 12 + j * 4 + 0] * inv;
            o.y = O[i * 12 + j * 4 + 1] * inv;
            o.z = O[i * 12 + j * 4 + 2] * inv;
            o.w = O[i * 12 + j * 4 + 3] * inv;
            *(float4*)(dst + j * 4) = o;
        }
    }
}

// ---------------------------------------------------------------------------
// Launch
// ---------------------------------------------------------------------------
extern "C" void kernel_launch(void* const* d_in, const int* in_sizes, int n_in,
                              void* d_out, int out_size) {
    const float* samples = (const float*)d_in[0];
    const float* Wq = (const float*)d_in[1];
    const float* bq = (const float*)d_in[2];
    const float* Wk = (const float*)d_in[3];
    const float* bk = (const float*)d_in[4];
    const float* Wv = (const float*)d_in[5];
    const float* bv = (const float*)d_in[6];
    const float* Wo = (const float*)d_in[7];
    const float* bo = (const float*)d_in[8];

    float *Qb, *Kb, *Vb, *Cb;
    cudaGetSymbolAddress((void**)&Qb, g_Q);
    cudaGetSymbolAddress((void**)&Kb, g_K);
    cudaGetSymbolAddress((void**)&Vb, g_V);
    cudaGetSymbolAddress((void**)&Cb, g_Ctx);

    // QKV projections: [16384,1536] @ [1536,768]
    dim3 gproj(DMODEL / GBN, MROWS / GBM);   // (6, 128)
    sgemm_bias<<<gproj, 256>>>(samples, Wq, bq, Qb, MROWS, DMODEL, DIN);
    sgemm_bias<<<gproj, 256>>>(samples, Wk, bk, Kb, MROWS, DMODEL, DIN);
    sgemm_bias<<<gproj, 256>>>(samples, Wv, bv, Vb, MROWS, DMODEL, DIN);

    // Attention
    cudaFuncSetAttribute(attn_kernel, cudaFuncAttributeMaxDynamicSharedMemorySize,
                         ATTN_SMEM_BYTES);
    dim3 gattn(LSEQ / BQ, BATCH * NHEADS);   // (32, 32)
    attn_kernel<<<gattn, 256, ATTN_SMEM_BYTES>>>(Qb, Kb, Vb, Cb);

    // Output projection: [16384,768] @ [768,768] -> d_out
    sgemm_bias<<<gproj, 256>>>(Cb, Wo, bo, (float*)d_out, MROWS, DMODEL, DMODEL);
}

// round 6
// speedup vs baseline: 1.4577x; 1.4577x over previous
#include <cuda_runtime.h>
#include <cuda_bf16.h>
#include <cstdint>

// Problem dims (fixed by the reference)
#define BATCH   8
#define LSEQ    2048
#define DMODEL  768
#define DIN     1536
#define NHEADS  4
#define DHEAD   192
#define MROWS   (BATCH * LSEQ)   // 16384
#define NQKV    (3 * DMODEL)     // 2304

// ---------------------------------------------------------------------------
// Scratch (allocation-free rule: __device__ globals)
// ---------------------------------------------------------------------------
__device__ float g_Q[MROWS * DMODEL];
__device__ float g_K[MROWS * DMODEL];
__device__ float g_V[MROWS * DMODEL];
__device__ __nv_bfloat16 g_Ahi[MROWS * DIN];
__device__ __nv_bfloat16 g_Alo[MROWS * DIN];
__device__ __nv_bfloat16 g_Wqkv_hi[NQKV * DIN];    // [n][k] K-major
__device__ __nv_bfloat16 g_Wqkv_lo[NQKV * DIN];
__device__ __nv_bfloat16 g_Wo_hi[DMODEL * DMODEL]; // [n][k] K-major
__device__ __nv_bfloat16 g_Wo_lo[DMODEL * DMODEL];
__device__ float g_bqkv[NQKV];
__device__ __nv_bfloat16 g_Chi[MROWS * DMODEL];
__device__ __nv_bfloat16 g_Clo[MROWS * DMODEL];

// ---------------------------------------------------------------------------
// Base-ISA helpers: mma.sync (sm_80 path), ldmatrix, cp.async
// ---------------------------------------------------------------------------
__device__ __forceinline__ uint32_t smem_to_u32(const void* p) {
    uint32_t a;
    asm("{ .reg .u64 t; cvta.to.shared.u64 t, %1; cvt.u32.u64 %0, t; }"
        : "=r"(a) : "l"(p));
    return a;
}
__device__ __forceinline__ void ldsm4(uint32_t* r, uint32_t addr) {
    asm volatile("ldmatrix.sync.aligned.m8n8.x4.shared.b16 {%0,%1,%2,%3}, [%4];"
                 : "=r"(r[0]), "=r"(r[1]), "=r"(r[2]), "=r"(r[3]) : "r"(addr));
}
__device__ __forceinline__ void mma_bf16(float* c, const uint32_t* a, const uint32_t* b) {
    asm volatile(
        "mma.sync.aligned.m16n8k16.row.col.f32.bf16.bf16.f32 "
        "{%0,%1,%2,%3}, {%4,%5,%6,%7}, {%8,%9}, {%0,%1,%2,%3};"
        : "+f"(c[0]), "+f"(c[1]), "+f"(c[2]), "+f"(c[3])
        : "r"(a[0]), "r"(a[1]), "r"(a[2]), "r"(a[3]), "r"(b[0]), "r"(b[1]));
}
__device__ __forceinline__ void cpasync16(uint32_t saddr, const void* g) {
    asm volatile("cp.async.cg.shared.global [%0], [%1], 16;" :: "r"(saddr), "l"(g));
}
#define CP_COMMIT() asm volatile("cp.async.commit_group;" ::: "memory")
#define CP_WAIT1()  asm volatile("cp.async.wait_group 1;" ::: "memory")

// ---------------------------------------------------------------------------
// Preprocessing: fp32 -> (hi, lo) bf16 split
// ---------------------------------------------------------------------------
__device__ __forceinline__ void split_bf16(float v, __nv_bfloat16& h, __nv_bfloat16& l) {
    h = __float2bfloat16(v);
    l = __float2bfloat16(v - __bfloat162float(h));
}

__global__ void conv_samples(const float4* __restrict__ src, int n4) {
    int i = blockIdx.x * 256 + threadIdx.x;
    if (i >= n4) return;
    float4 v = src[i];
    __nv_bfloat16 h0, h1, h2, h3, l0, l1, l2, l3;
    split_bf16(v.x, h0, l0); split_bf16(v.y, h1, l1);
    split_bf16(v.z, h2, l2); split_bf16(v.w, h3, l3);
    *(__nv_bfloat162*)(g_Ahi + 4 * (size_t)i)     = __halves2bfloat162(h0, h1);
    *(__nv_bfloat162*)(g_Ahi + 4 * (size_t)i + 2) = __halves2bfloat162(h2, h3);
    *(__nv_bfloat162*)(g_Alo + 4 * (size_t)i)     = __halves2bfloat162(l0, l1);
    *(__nv_bfloat162*)(g_Alo + 4 * (size_t)i + 2) = __halves2bfloat162(l2, l3);
}

__global__ void conv_wqkv(const float* __restrict__ Wq, const float* __restrict__ Wk,
                          const float* __restrict__ Wv,
                          const float* __restrict__ bq, const float* __restrict__ bk,
                          const float* __restrict__ bv) {
    int i = blockIdx.x * 256 + threadIdx.x;
    if (i >= NQKV * DIN) return;
    int n = i / DIN, k = i % DIN;
    const float* W = (n < DMODEL) ? Wq : (n < 2 * DMODEL) ? Wk : Wv;
    int nc = n % DMODEL;
    float v = W[(size_t)k * DMODEL + nc];
    __nv_bfloat16 h, l; split_bf16(v, h, l);
    g_Wqkv_hi[i] = h; g_Wqkv_lo[i] = l;
    if (i < NQKV)
        g_bqkv[i] = (i < DMODEL) ? bq[i] : (i < 2 * DMODEL) ? bk[i - DMODEL] : bv[i - 2 * DMODEL];
}

__global__ void conv_wo(const float* __restrict__ Wo) {
    int i = blockIdx.x * 256 + threadIdx.x;
    if (i >= DMODEL * DMODEL) return;
    int n = i / DMODEL, k = i % DMODEL;
    float v = Wo[(size_t)k * DMODEL + n];
    __nv_bfloat16 h, l; split_bf16(v, h, l);
    g_Wo_hi[i] = h; g_Wo_lo[i] = l;
}

// ---------------------------------------------------------------------------
// mma.sync split-bf16 GEMM: C[M,N] = A[M,K] @ W[K,N] + bias
// A,W as (hi,lo) bf16, W pre-transposed [N][K] K-major.
// CTA 128x128, BK=32, 8 warps (2x4), warp tile 64x32.
// 3-stage cp.async pipeline. 3 MMA chains: AhBh + AhBl + AlBh (fp32 accum).
// Smem tiles padded to 40 bf16/row (80B) -> ldmatrix conflict-free.
// ---------------------------------------------------------------------------
#define TROW    40                       // padded row stride (bf16 elems)
#define TILE_B  (128 * TROW * 2)         // 10240 B per tile
#define STAGE_B (4 * TILE_B)             // Ah | Al | Bh | Bl = 40960 B
#define NSTAGE  3
#define GEMM_SMEM (NSTAGE * STAGE_B)     // 122880 B

__device__ __forceinline__ void issue_stage(
    uint32_t sbase, const __nv_bfloat16* __restrict__ Ah,
    const __nv_bfloat16* __restrict__ Al, const __nv_bfloat16* __restrict__ Bh,
    const __nv_bfloat16* __restrict__ Bl, int row0, int n0g, int k0, int K, int tid) {
    const __nv_bfloat16* srcs[4] = {Ah, Al, Bh, Bl};
#pragma unroll
    for (int t = 0; t < 8; t++) {
        int c    = tid + t * 256;        // 0..2047
        int tile = c >> 9;               // 0..3
        int idx  = c & 511;
        int row  = idx >> 2;             // 0..127
        int kc   = (idx & 3) * 8;        // element offset
        int grow = ((tile < 2) ? row0 : n0g) + row;
        const __nv_bfloat16* g = srcs[tile] + (size_t)grow * K + k0 + kc;
        uint32_t saddr = sbase + tile * TILE_B + (uint32_t)(row * TROW + kc) * 2;
        cpasync16(saddr, g);
    }
}

__global__ __launch_bounds__(256, 1)
void gemm_hilo(const __nv_bfloat16* __restrict__ Ah, const __nv_bfloat16* __restrict__ Al,
               const __nv_bfloat16* __restrict__ Bh, const __nv_bfloat16* __restrict__ Bl,
               const float* __restrict__ bias,
               float* outQ, float* outK, float* outV,
               int K, int Nout, int ntpm) {
    extern __shared__ char smem[];
    const uint32_t smem_u = smem_to_u32(smem);
    const int tid  = threadIdx.x;
    const int wid  = tid >> 5;
    const int lane = tid & 31;
    const int bx = blockIdx.x, by = blockIdx.y;

    const int mat = bx / ntpm;
    float* outs = (mat == 0) ? outQ : (mat == 1) ? outK : outV;
    const int row0 = by * 128;
    const int n0g  = bx * 128;             // B row base (concat) / bias base
    const int n0   = (bx % ntpm) * 128;    // C col base within matrix

    const int wm = wid >> 2;               // 0..1 -> 64 rows
    const int wn = wid & 3;                // 0..3 -> 32 cols

    const int ns = K / 32;

    // Prologue: stages 0,1
    issue_stage(smem_u, Ah, Al, Bh, Bl, row0, n0g, 0, K, tid);
    CP_COMMIT();
    issue_stage(smem_u + STAGE_B, Ah, Al, Bh, Bl, row0, n0g, 32, K, tid);
    CP_COMMIT();

    float c[4][4][4];
#pragma unroll
    for (int i = 0; i < 4; i++)
#pragma unroll
        for (int j = 0; j < 4; j++)
#pragma unroll
            for (int q = 0; q < 4; q++) c[i][j][q] = 0.f;

    // ldmatrix lane addressing (elements)
    const int a_row = lane & 15;                    // 0..15
    const int a_kad = (lane >> 4) * 8;              // 0 or 8
    const int b_r   = lane & 7;
    const int b_q   = lane >> 3;
    const int b_nad = (b_q >> 1) * 8;               // 0 or 8
    const int b_kad = (b_q & 1) * 8;                // 0 or 8

    for (int s = 0; s < ns; s++) {
        CP_WAIT1();
        __syncthreads();
        if (s + 2 < ns)
            issue_stage(smem_u + ((s + 2) % NSTAGE) * STAGE_B,
                        Ah, Al, Bh, Bl, row0, n0g, (s + 2) * 32, K, tid);
        CP_COMMIT();

        const uint32_t sb  = smem_u + (s % NSTAGE) * STAGE_B;
        const uint32_t sAh = sb;
        const uint32_t sAl = sb + TILE_B;
        const uint32_t sBh = sb + 2 * TILE_B;
        const uint32_t sBl = sb + 3 * TILE_B;

#pragma unroll
        for (int ks = 0; ks < 2; ks++) {
            uint32_t ah[4][4], al[4][4], bh[2][4], bl[2][4];
#pragma unroll
            for (int mf = 0; mf < 4; mf++) {
                uint32_t off = ((uint32_t)((wm * 64 + mf * 16 + a_row) * TROW
                                           + ks * 16 + a_kad)) * 2;
                ldsm4(ah[mf], sAh + off);
                ldsm4(al[mf], sAl + off);
            }
#pragma unroll
            for (int np = 0; np < 2; np++) {
                uint32_t off = ((uint32_t)((wn * 32 + np * 16 + b_r + b_nad) * TROW
                                           + ks * 16 + b_kad)) * 2;
                ldsm4(bh[np], sBh + off);
                ldsm4(bl[np], sBl + off);
            }
#pragma unroll
            for (int mf = 0; mf < 4; mf++)
#pragma unroll
                for (int nf = 0; nf < 4; nf++) {
                    const int np = nf >> 1, bo = (nf & 1) * 2;
                    mma_bf16(c[mf][nf], ah[mf], &bh[np][bo]);
                    mma_bf16(c[mf][nf], ah[mf], &bl[np][bo]);
                    mma_bf16(c[mf][nf], al[mf], &bh[np][bo]);
                }
        }
        __syncthreads();
    }

    // Epilogue: registers -> global with bias (C frag: rows g,g+8; cols 2tg,2tg+1)
    const int g  = lane >> 2;
    const int tg = lane & 3;
#pragma unroll
    for (int nf = 0; nf < 4; nf++) {
        const int colL = wn * 32 + nf * 8 + 2 * tg;
        const float b0 = bias[n0g + colL];
        const float b1 = bias[n0g + colL + 1];
#pragma unroll
        for (int mf = 0; mf < 4; mf++) {
            const int row = row0 + wm * 64 + mf * 16 + g;
            float2 v0 = {c[mf][nf][0] + b0, c[mf][nf][1] + b1};
            float2 v1 = {c[mf][nf][2] + b0, c[mf][nf][3] + b1};
            *(float2*)(outs + (size_t)row * Nout + n0 + colL)       = v0;
            *(float2*)(outs + (size_t)(row + 8) * Nout + n0 + colL) = v1;
        }
    }
}

// ---------------------------------------------------------------------------
// Flash attention (fp32, unscaled logits, online softmax).
// Epilogue emits ctx as (hi,lo) bf16 for the tensor-core out-projection.
// ---------------------------------------------------------------------------
#define BQ  64
#define BS  32
#define QST 65
#define KST 33
#define VST 196
#define SST 33

#define ATTN_SMEM_FLOATS (DHEAD*QST + DHEAD*KST + BS*VST + BQ*SST + 3*BQ)
#define ATTN_SMEM_BYTES  (ATTN_SMEM_FLOATS * 4)

__global__ __launch_bounds__(256, 2)
void attn_kernel(const float* __restrict__ Q, const float* __restrict__ K,
                 const float* __restrict__ V) {
    extern __shared__ float sm[];
    float* Qst    = sm;
    float* Kst    = Qst + DHEAD * QST;
    float* Vs     = Kst + DHEAD * KST;
    float* Ss     = Vs + BS * VST;
    float* ms     = Ss + BQ * SST;
    float* ls     = ms + BQ;
    float* alphas = ls + BQ;

    const int tid   = threadIdx.x;
    const int qtile = blockIdx.x;
    const int bh    = blockIdx.y;
    const int b     = bh / NHEADS;
    const int h     = bh % NHEADS;

    const float* Qg = Q + (size_t)b * LSEQ * DMODEL + h * DHEAD;
    const float* Kg = K + (size_t)b * LSEQ * DMODEL + h * DHEAD;
    const float* Vg = V + (size_t)b * LSEQ * DMODEL + h * DHEAD;

    for (int i = tid; i < BQ * 48; i += 256) {
        const int r  = i / 48;
        const int dc = (i % 48) * 4;
        float4 q4 = *(const float4*)(Qg + (size_t)(qtile * BQ + r) * DMODEL + dc);
        Qst[(dc + 0) * QST + r] = q4.x;
        Qst[(dc + 1) * QST + r] = q4.y;
        Qst[(dc + 2) * QST + r] = q4.z;
        Qst[(dc + 3) * QST + r] = q4.w;
    }
    if (tid < BQ) { ms[tid] = -1e30f; ls[tid] = 0.f; }

    const int rg  = tid >> 4;
    const int r0  = rg * 4;
    const int kk0 = tid & 15;
    const int dc0 = (tid & 15) * 12;

    float O[48];
#pragma unroll
    for (int i = 0; i < 48; i++) O[i] = 0.f;

    for (int t = 0; t < LSEQ / BS; t++) {
        __syncthreads();

        for (int i = tid; i < BS * 48; i += 256) {
            const int kr = i / 48;
            const int dc = (i % 48) * 4;
            float4 k4 = *(const float4*)(Kg + (size_t)(t * BS + kr) * DMODEL + dc);
            Kst[(dc + 0) * KST + kr] = k4.x;
            Kst[(dc + 1) * KST + kr] = k4.y;
            Kst[(dc + 2) * KST + kr] = k4.z;
            Kst[(dc + 3) * KST + kr] = k4.w;
            float4 v4 = *(const float4*)(Vg + (size_t)(t * BS + kr) * DMODEL + dc);
            *(float4*)(Vs + kr * VST + dc) = v4;
        }
        __syncthreads();

        float acc[4][2];
#pragma unroll
        for (int i = 0; i < 4; i++) { acc[i][0] = 0.f; acc[i][1] = 0.f; }
#pragma unroll 4
        for (int d = 0; d < DHEAD; d++) {
            const float kv0 = Kst[d * KST + kk0];
            const float kv1 = Kst[d * KST + kk0 + 16];
#pragma unroll
            for (int i = 0; i < 4; i++) {
                const float qv = Qst[d * QST + r0 + i];
                acc[i][0] += qv * kv0;
                acc[i][1] += qv * kv1;
            }
        }
#pragma unroll
        for (int i = 0; i < 4; i++) {
            Ss[(r0 + i) * SST + kk0]      = acc[i][0];
            Ss[(r0 + i) * SST + kk0 + 16] = acc[i][1];
        }
        __syncthreads();

        if (tid < BQ) {
            const float m_old = ms[tid];
            float tmax = m_old;
#pragma unroll
            for (int k = 0; k < BS; k++) tmax = fmaxf(tmax, Ss[tid * SST + k]);
            ms[tid] = tmax;
            alphas[tid] = __expf(m_old - tmax);
        }
        __syncthreads();

#pragma unroll
        for (int i = 0; i < 4; i++) {
            const float mrow = ms[r0 + i];
            Ss[(r0 + i) * SST + kk0]      = __expf(acc[i][0] - mrow);
            Ss[(r0 + i) * SST + kk0 + 16] = __expf(acc[i][1] - mrow);
        }
        __syncthreads();

        if (tid < BQ) {
            float s = 0.f;
#pragma unroll
            for (int k = 0; k < BS; k++) s += Ss[tid * SST + k];
            ls[tid] = ls[tid] * alphas[tid] + s;
        }

        float al[4];
#pragma unroll
        for (int i = 0; i < 4; i++) al[i] = alphas[r0 + i];
#pragma unroll
        for (int i = 0; i < 4; i++)
#pragma unroll
            for (int j = 0; j < 12; j++) O[i * 12 + j] *= al[i];

#pragma unroll 2
        for (int k = 0; k < BS; k++) {
            float p[4];
#pragma unroll
            for (int i = 0; i < 4; i++) p[i] = Ss[(r0 + i) * SST + k];
            const float4 v0 = *(const float4*)(Vs + k * VST + dc0);
            const float4 v1 = *(const float4*)(Vs + k * VST + dc0 + 4);
            const float4 v2 = *(const float4*)(Vs + k * VST + dc0 + 8);
#pragma unroll
            for (int i = 0; i < 4; i++) {
                O[i * 12 + 0]  += p[i] * v0.x;
                O[i * 12 + 1]  += p[i] * v0.y;
                O[i * 12 + 2]  += p[i] * v0.z;
                O[i * 12 + 3]  += p[i] * v0.w;
                O[i * 12 + 4]  += p[i] * v1.x;
                O[i * 12 + 5]  += p[i] * v1.y;
                O[i * 12 + 6]  += p[i] * v1.z;
                O[i * 12 + 7]  += p[i] * v1.w;
                O[i * 12 + 8]  += p[i] * v2.x;
                O[i * 12 + 9]  += p[i] * v2.y;
                O[i * 12 + 10] += p[i] * v2.z;
                O[i * 12 + 11] += p[i] * v2.w;
            }
        }
    }
    __syncthreads();

    // ctx -> (hi, lo) bf16 split, consumed by out-projection GEMM
#pragma unroll
    for (int i = 0; i < 4; i++) {
        const float inv = 1.f / ls[r0 + i];
        const int row = qtile * BQ + r0 + i;
        const size_t base = ((size_t)b * LSEQ + row) * DMODEL + h * DHEAD + dc0;
#pragma unroll
        for (int j = 0; j < 6; j++) {
            float v0 = O[i * 12 + j * 2]     * inv;
            float v1 = O[i * 12 + j * 2 + 1] * inv;
            __nv_bfloat16 h0, h1, l0, l1;
            split_bf16(v0, h0, l0);
            split_bf16(v1, h1, l1);
            *(__nv_bfloat162*)(g_Chi + base + j * 2) = __halves2bfloat162(h0, h1);
            *(__nv_bfloat162*)(g_Clo + base + j * 2) = __halves2bfloat162(l0, l1);
        }
    }
}

// ---------------------------------------------------------------------------
// Launch
// ---------------------------------------------------------------------------
extern "C" void kernel_launch(void* const* d_in, const int* in_sizes, int n_in,
                              void* d_out, int out_size) {
    const float* samples = (const float*)d_in[0];
    const float* Wq = (const float*)d_in[1];
    const float* bq = (const float*)d_in[2];
    const float* Wk = (const float*)d_in[3];
    const float* bk = (const float*)d_in[4];
    const float* Wv = (const float*)d_in[5];
    const float* bv = (const float*)d_in[6];
    const float* Wo = (const float*)d_in[7];
    const float* bo = (const float*)d_in[8];

    float *Qb, *Kb, *Vb, *bqkv;
    __nv_bfloat16 *Ahi, *Alo, *Wqh, *Wql, *Woh, *Wol, *Chi, *Clo;
    cudaGetSymbolAddress((void**)&Qb,   g_Q);
    cudaGetSymbolAddress((void**)&Kb,   g_K);
    cudaGetSymbolAddress((void**)&Vb,   g_V);
    cudaGetSymbolAddress((void**)&bqkv, g_bqkv);
    cudaGetSymbolAddress((void**)&Ahi,  g_Ahi);
    cudaGetSymbolAddress((void**)&Alo,  g_Alo);
    cudaGetSymbolAddress((void**)&Wqh,  g_Wqkv_hi);
    cudaGetSymbolAddress((void**)&Wql,  g_Wqkv_lo);
    cudaGetSymbolAddress((void**)&Woh,  g_Wo_hi);
    cudaGetSymbolAddress((void**)&Wol,  g_Wo_lo);
    cudaGetSymbolAddress((void**)&Chi,  g_Chi);
    cudaGetSymbolAddress((void**)&Clo,  g_Clo);

    // Preprocess: split fp32 -> (hi,lo) bf16; transpose weights to [N][K]
    {
        int n4 = MROWS * DIN / 4;
        conv_samples<<<(n4 + 255) / 256, 256>>>((const float4*)samples, n4);
        int nw = NQKV * DIN;
        conv_wqkv<<<(nw + 255) / 256, 256>>>(Wq, Wk, Wv, bq, bk, bv);
        int no = DMODEL * DMODEL;
        conv_wo<<<(no + 255) / 256, 256>>>(Wo);
    }

    cudaFuncSetAttribute(gemm_hilo, cudaFuncAttributeMaxDynamicSharedMemorySize, GEMM_SMEM);

    // Fused QKV projection: [16384,1536] @ [1536, 3*768]
    gemm_hilo<<<dim3(NQKV / 128, MROWS / 128), 256, GEMM_SMEM>>>(
        Ahi, Alo, Wqh, Wql, bqkv, Qb, Kb, Vb, DIN, DMODEL, DMODEL / 128);

    // Attention
    cudaFuncSetAttribute(attn_kernel, cudaFuncAttributeMaxDynamicSharedMemorySize,
                         ATTN_SMEM_BYTES);
    dim3 gattn(LSEQ / BQ, BATCH * NHEADS);
    attn_kernel<<<gattn, 256, ATTN_SMEM_BYTES>>>(Qb, Kb, Vb);

    // Output projection: [16384,768] @ [768,768] -> d_out
    gemm_hilo<<<dim3(DMODEL / 128, MROWS / 128), 256, GEMM_SMEM>>>(
        Chi, Clo, Woh, Wol, bo, (float*)d_out, (float*)d_out, (float*)d_out,
        DMODEL, DMODEL, DMODEL / 128);
}

// round 7
// speedup vs baseline: 2.9187x; 2.0022x over previous
#include <cuda_runtime.h>
#include <cuda_bf16.h>
#include <cstdint>

// Problem dims (fixed by the reference)
#define BATCH   8
#define LSEQ    2048
#define DMODEL  768
#define DIN     1536
#define NHEADS  4
#define DHEAD   192
#define MROWS   (BATCH * LSEQ)   // 16384
#define NQKV    (3 * DMODEL)     // 2304

// ---------------------------------------------------------------------------
// Scratch (allocation-free rule: __device__ globals)
// ---------------------------------------------------------------------------
__device__ __nv_bfloat16 g_Ahi[MROWS * DIN];
__device__ __nv_bfloat16 g_Alo[MROWS * DIN];
__device__ __nv_bfloat16 g_Wqkv_hi[NQKV * DIN];    // [n][k] K-major
__device__ __nv_bfloat16 g_Wqkv_lo[NQKV * DIN];
__device__ __nv_bfloat16 g_Wo_hi[DMODEL * DMODEL]; // [n][k] K-major
__device__ __nv_bfloat16 g_Wo_lo[DMODEL * DMODEL];
__device__ float g_bqkv[NQKV];
__device__ __nv_bfloat16 g_Qh[MROWS * DMODEL];
__device__ __nv_bfloat16 g_Ql[MROWS * DMODEL];
__device__ __nv_bfloat16 g_Kh[MROWS * DMODEL];
__device__ __nv_bfloat16 g_Kl[MROWS * DMODEL];
__device__ __nv_bfloat16 g_Vh[MROWS * DMODEL];
__device__ __nv_bfloat16 g_Vl[MROWS * DMODEL];
__device__ __nv_bfloat16 g_Chi[MROWS * DMODEL];
__device__ __nv_bfloat16 g_Clo[MROWS * DMODEL];

// ---------------------------------------------------------------------------
// Base-ISA helpers: mma.sync, ldmatrix, cp.async
// ---------------------------------------------------------------------------
__device__ __forceinline__ uint32_t smem_to_u32(const void* p) {
    uint32_t a;
    asm("{ .reg .u64 t; cvta.to.shared.u64 t, %1; cvt.u32.u64 %0, t; }"
        : "=r"(a) : "l"(p));
    return a;
}
__device__ __forceinline__ void ldsm4(uint32_t* r, uint32_t addr) {
    asm volatile("ldmatrix.sync.aligned.m8n8.x4.shared.b16 {%0,%1,%2,%3}, [%4];"
                 : "=r"(r[0]), "=r"(r[1]), "=r"(r[2]), "=r"(r[3]) : "r"(addr));
}
__device__ __forceinline__ void ldsm4t(uint32_t* r, uint32_t addr) {
    asm volatile("ldmatrix.sync.aligned.m8n8.x4.trans.shared.b16 {%0,%1,%2,%3}, [%4];"
                 : "=r"(r[0]), "=r"(r[1]), "=r"(r[2]), "=r"(r[3]) : "r"(addr));
}
__device__ __forceinline__ void mma_bf16(float* c, const uint32_t* a, const uint32_t* b) {
    asm volatile(
        "mma.sync.aligned.m16n8k16.row.col.f32.bf16.bf16.f32 "
        "{%0,%1,%2,%3}, {%4,%5,%6,%7}, {%8,%9}, {%0,%1,%2,%3};"
        : "+f"(c[0]), "+f"(c[1]), "+f"(c[2]), "+f"(c[3])
        : "r"(a[0]), "r"(a[1]), "r"(a[2]), "r"(a[3]), "r"(b[0]), "r"(b[1]));
}
__device__ __forceinline__ void cpasync16(uint32_t saddr, const void* g) {
    asm volatile("cp.async.cg.shared.global [%0], [%1], 16;" :: "r"(saddr), "l"(g));
}
#define CP_COMMIT() asm volatile("cp.async.commit_group;" ::: "memory")
#define CP_WAIT1()  asm volatile("cp.async.wait_group 1;" ::: "memory")

__device__ __forceinline__ void split_bf16(float v, __nv_bfloat16& h, __nv_bfloat16& l) {
    h = __float2bfloat16(v);
    l = __float2bfloat16(v - __bfloat162float(h));
}
__device__ __forceinline__ uint32_t pack2(__nv_bfloat16 a, __nv_bfloat16 b) {
    __nv_bfloat162 t = __halves2bfloat162(a, b);
    return *(uint32_t*)&t;
}

// ---------------------------------------------------------------------------
// Preprocessing
// ---------------------------------------------------------------------------
__global__ void conv_samples(const float4* __restrict__ src, int n4) {
    int i = blockIdx.x * 256 + threadIdx.x;
    if (i >= n4) return;
    float4 v = src[i];
    __nv_bfloat16 h0, h1, h2, h3, l0, l1, l2, l3;
    split_bf16(v.x, h0, l0); split_bf16(v.y, h1, l1);
    split_bf16(v.z, h2, l2); split_bf16(v.w, h3, l3);
    *(__nv_bfloat162*)(g_Ahi + 4 * (size_t)i)     = __halves2bfloat162(h0, h1);
    *(__nv_bfloat162*)(g_Ahi + 4 * (size_t)i + 2) = __halves2bfloat162(h2, h3);
    *(__nv_bfloat162*)(g_Alo + 4 * (size_t)i)     = __halves2bfloat162(l0, l1);
    *(__nv_bfloat162*)(g_Alo + 4 * (size_t)i + 2) = __halves2bfloat162(l2, l3);
}

__global__ void conv_wqkv(const float* __restrict__ Wq, const float* __restrict__ Wk,
                          const float* __restrict__ Wv,
                          const float* __restrict__ bq, const float* __restrict__ bk,
                          const float* __restrict__ bv) {
    int i = blockIdx.x * 256 + threadIdx.x;
    if (i >= NQKV * DIN) return;
    int n = i / DIN, k = i % DIN;
    const float* W = (n < DMODEL) ? Wq : (n < 2 * DMODEL) ? Wk : Wv;
    int nc = n % DMODEL;
    float v = W[(size_t)k * DMODEL + nc];
    __nv_bfloat16 h, l; split_bf16(v, h, l);
    g_Wqkv_hi[i] = h; g_Wqkv_lo[i] = l;
    if (i < NQKV)
        g_bqkv[i] = (i < DMODEL) ? bq[i] : (i < 2 * DMODEL) ? bk[i - DMODEL] : bv[i - 2 * DMODEL];
}

__global__ void conv_wo(const float* __restrict__ Wo) {
    int i = blockIdx.x * 256 + threadIdx.x;
    if (i >= DMODEL * DMODEL) return;
    int n = i / DMODEL, k = i % DMODEL;
    float v = Wo[(size_t)k * DMODEL + n];
    __nv_bfloat16 h, l; split_bf16(v, h, l);
    g_Wo_hi[i] = h; g_Wo_lo[i] = l;
}

// ---------------------------------------------------------------------------
// mma.sync split-bf16 GEMM: C[M,N] = A[M,K] @ W[K,N] + bias
// BF16OUT: write (hi,lo) bf16 to per-matrix outputs; else fp32 to outF.
// ---------------------------------------------------------------------------
#define TROW    40
#define TILE_B  (128 * TROW * 2)
#define STAGE_B (4 * TILE_B)
#define NSTAGE  3
#define GEMM_SMEM (NSTAGE * STAGE_B)

__device__ __forceinline__ void issue_stage(
    uint32_t sbase, const __nv_bfloat16* __restrict__ Ah,
    const __nv_bfloat16* __restrict__ Al, const __nv_bfloat16* __restrict__ Bh,
    const __nv_bfloat16* __restrict__ Bl, int row0, int n0g, int k0, int K, int tid) {
    const __nv_bfloat16* srcs[4] = {Ah, Al, Bh, Bl};
#pragma unroll
    for (int t = 0; t < 8; t++) {
        int c    = tid + t * 256;
        int tile = c >> 9;
        int idx  = c & 511;
        int row  = idx >> 2;
        int kc   = (idx & 3) * 8;
        int grow = ((tile < 2) ? row0 : n0g) + row;
        const __nv_bfloat16* g = srcs[tile] + (size_t)grow * K + k0 + kc;
        uint32_t saddr = sbase + tile * TILE_B + (uint32_t)(row * TROW + kc) * 2;
        cpasync16(saddr, g);
    }
}

template <bool BF16OUT>
__global__ __launch_bounds__(256, 1)
void gemm_hilo(const __nv_bfloat16* __restrict__ Ah, const __nv_bfloat16* __restrict__ Al,
               const __nv_bfloat16* __restrict__ Bh, const __nv_bfloat16* __restrict__ Bl,
               const float* __restrict__ bias, float* outF,
               __nv_bfloat16* o0h, __nv_bfloat16* o0l,
               __nv_bfloat16* o1h, __nv_bfloat16* o1l,
               __nv_bfloat16* o2h, __nv_bfloat16* o2l,
               int K, int Nout, int ntpm) {
    extern __shared__ char smem[];
    const uint32_t smem_u = smem_to_u32(smem);
    const int tid  = threadIdx.x;
    const int lane = tid & 31;
    const int wid  = tid >> 5;
    const int bx = blockIdx.x, by = blockIdx.y;

    const int mat = bx / ntpm;
    const int row0 = by * 128;
    const int n0g  = bx * 128;
    const int n0   = (bx % ntpm) * 128;

    const int wm = wid >> 2;
    const int wn = wid & 3;
    const int ns = K / 32;

    issue_stage(smem_u, Ah, Al, Bh, Bl, row0, n0g, 0, K, tid);
    CP_COMMIT();
    issue_stage(smem_u + STAGE_B, Ah, Al, Bh, Bl, row0, n0g, 32, K, tid);
    CP_COMMIT();

    float c[4][4][4];
#pragma unroll
    for (int i = 0; i < 4; i++)
#pragma unroll
        for (int j = 0; j < 4; j++)
#pragma unroll
            for (int q = 0; q < 4; q++) c[i][j][q] = 0.f;

    const int a_row = lane & 15;
    const int a_kad = (lane >> 4) * 8;
    const int b_r   = lane & 7;
    const int b_q   = lane >> 3;
    const int b_nad = (b_q >> 1) * 8;
    const int b_kad = (b_q & 1) * 8;

    for (int s = 0; s < ns; s++) {
        CP_WAIT1();
        __syncthreads();
        if (s + 2 < ns)
            issue_stage(smem_u + ((s + 2) % NSTAGE) * STAGE_B,
                        Ah, Al, Bh, Bl, row0, n0g, (s + 2) * 32, K, tid);
        CP_COMMIT();

        const uint32_t sb  = smem_u + (s % NSTAGE) * STAGE_B;
        const uint32_t sAh = sb;
        const uint32_t sAl = sb + TILE_B;
        const uint32_t sBh = sb + 2 * TILE_B;
        const uint32_t sBl = sb + 3 * TILE_B;

#pragma unroll
        for (int ks = 0; ks < 2; ks++) {
            uint32_t ah[4][4], al[4][4], bh[2][4], bl[2][4];
#pragma unroll
            for (int mf = 0; mf < 4; mf++) {
                uint32_t off = ((uint32_t)((wm * 64 + mf * 16 + a_row) * TROW
                                           + ks * 16 + a_kad)) * 2;
                ldsm4(ah[mf], sAh + off);
                ldsm4(al[mf], sAl + off);
            }
#pragma unroll
            for (int np = 0; np < 2; np++) {
                uint32_t off = ((uint32_t)((wn * 32 + np * 16 + b_r + b_nad) * TROW
                                           + ks * 16 + b_kad)) * 2;
                ldsm4(bh[np], sBh + off);
                ldsm4(bl[np], sBl + off);
            }
#pragma unroll
            for (int mf = 0; mf < 4; mf++)
#pragma unroll
                for (int nf = 0; nf < 4; nf++) {
                    const int np = nf >> 1, bo = (nf & 1) * 2;
                    mma_bf16(c[mf][nf], ah[mf], &bh[np][bo]);
                    mma_bf16(c[mf][nf], ah[mf], &bl[np][bo]);
                    mma_bf16(c[mf][nf], al[mf], &bh[np][bo]);
                }
        }
        __syncthreads();
    }

    const int g  = lane >> 2;
    const int tg = lane & 3;
#pragma unroll
    for (int nf = 0; nf < 4; nf++) {
        const int colL = wn * 32 + nf * 8 + 2 * tg;
        const float b0 = bias[n0g + colL];
        const float b1 = bias[n0g + colL + 1];
#pragma unroll
        for (int mf = 0; mf < 4; mf++) {
            const int row = row0 + wm * 64 + mf * 16 + g;
            float f0 = c[mf][nf][0] + b0, f1 = c[mf][nf][1] + b1;
            float f2 = c[mf][nf][2] + b0, f3 = c[mf][nf][3] + b1;
            if (BF16OUT) {
                __nv_bfloat16* oh = (mat == 0) ? o0h : (mat == 1) ? o1h : o2h;
                __nv_bfloat16* ol = (mat == 0) ? o0l : (mat == 1) ? o1l : o2l;
                __nv_bfloat16 h0, h1, h2, h3, e0, e1, e2, e3;
                split_bf16(f0, h0, e0); split_bf16(f1, h1, e1);
                split_bf16(f2, h2, e2); split_bf16(f3, h3, e3);
                size_t p0 = (size_t)row * Nout + n0 + colL;
                size_t p1 = (size_t)(row + 8) * Nout + n0 + colL;
                *(__nv_bfloat162*)(oh + p0) = __halves2bfloat162(h0, h1);
                *(__nv_bfloat162*)(ol + p0) = __halves2bfloat162(e0, e1);
                *(__nv_bfloat162*)(oh + p1) = __halves2bfloat162(h2, h3);
                *(__nv_bfloat162*)(ol + p1) = __halves2bfloat162(e2, e3);
            } else {
                *(float2*)(outF + (size_t)row * Nout + n0 + colL)       = {f0, f1};
                *(float2*)(outF + (size_t)(row + 8) * Nout + n0 + colL) = {f2, f3};
            }
        }
    }
}

// ---------------------------------------------------------------------------
// Tensor-core flash attention (hi/lo bf16, fp32 accum, online softmax).
// CTA: 128 q-rows x one (b,h). 8 warps x 16 rows. Key tiles of 32,
// double-buffered cp.async. S frag layout == A frag layout for PV.
// ---------------------------------------------------------------------------
#define AROW      200                        // padded bf16 row stride (400 B)
#define AQ_BYTES  (128 * AROW * 2)           // 51200 per Q tensor
#define KV_TILE_B (32 * AROW * 2)            // 12800 per tensor-tile
#define STAGE_AB  (4 * KV_TILE_B)            // 51200
#define ATTN_SMEM (2 * AQ_BYTES + 2 * STAGE_AB)   // 204800
#define NKT       (LSEQ / 32)                // 64

__global__ __launch_bounds__(256, 1)
void attn_mma(const __nv_bfloat16* __restrict__ Qh, const __nv_bfloat16* __restrict__ Ql,
              const __nv_bfloat16* __restrict__ Kh, const __nv_bfloat16* __restrict__ Kl,
              const __nv_bfloat16* __restrict__ Vh, const __nv_bfloat16* __restrict__ Vl) {
    extern __shared__ char sm[];
    const uint32_t su = smem_to_u32(sm);
    const uint32_t sQh = su, sQl = su + AQ_BYTES;
    const uint32_t sStage = su + 2 * AQ_BYTES;

    const int tid = threadIdx.x, wid = tid >> 5, lane = tid & 31;
    const int qtile = blockIdx.x, bh = blockIdx.y;
    const int b = bh / NHEADS, h = bh % NHEADS;
    const size_t gbase = (size_t)b * LSEQ * DMODEL + h * DHEAD;

    const __nv_bfloat16* Qgh = Qh + gbase + (size_t)qtile * 128 * DMODEL;
    const __nv_bfloat16* Qgl = Ql + gbase + (size_t)qtile * 128 * DMODEL;
    const __nv_bfloat16* Kgh = Kh + gbase;
    const __nv_bfloat16* Kgl = Kl + gbase;
    const __nv_bfloat16* Vgh = Vh + gbase;
    const __nv_bfloat16* Vgl = Vl + gbase;

    // Load Q tile (hi/lo) into smem
    for (int i = tid; i < 2 * 3072; i += 256) {
        int tz = i / 3072, idx = i % 3072;
        int r = idx / 24, cc = (idx % 24) * 8;
        const __nv_bfloat16* src = (tz ? Qgl : Qgh) + (size_t)r * DMODEL + cc;
        uint4 v = *(const uint4*)src;
        *(uint4*)(sm + (tz ? AQ_BYTES : 0) + r * 400 + cc * 2) = v;
    }

    // Prologue KV stages 0,1
    const __nv_bfloat16* kvsrc[4] = {Kgh, Kgl, Vgh, Vgl};
#pragma unroll
    for (int st = 0; st < 2; st++) {
        uint32_t sb = sStage + st * STAGE_AB;
#pragma unroll
        for (int j = 0; j < 12; j++) {
            int i = tid + j * 256;
            int tz = i / 768, idx = i % 768;
            int r = idx / 24, cc = (idx % 24) * 8;
            cpasync16(sb + tz * KV_TILE_B + (uint32_t)(r * 400 + cc * 2),
                      kvsrc[tz] + (size_t)(st * 32 + r) * DMODEL + cc);
        }
        CP_COMMIT();
    }
    __syncthreads();

    const int a_row = lane & 15;
    const int a_k   = (lane >> 4) * 8;
    const int b_r   = lane & 7;
    const int b_q   = lane >> 3;
    const int b_n   = (b_q >> 1) * 8;
    const int b_k   = (b_q & 1) * 8;

    float O[24][4];
#pragma unroll
    for (int i = 0; i < 24; i++)
#pragma unroll
        for (int j = 0; j < 4; j++) O[i][j] = 0.f;
    float m_lo = -1e30f, m_hi = -1e30f, l_lo = 0.f, l_hi = 0.f;

    for (int t = 0; t < NKT; t++) {
        CP_WAIT1();
        __syncthreads();
        const uint32_t sb  = sStage + (t & 1) * STAGE_AB;
        const uint32_t sKh = sb, sKl = sb + KV_TILE_B;
        const uint32_t sVh = sb + 2 * KV_TILE_B, sVl = sb + 3 * KV_TILE_B;

        // ---- S = Q K^T (16 x 32 per warp), 3 chains ----
        float S[4][4];
#pragma unroll
        for (int i = 0; i < 4; i++)
#pragma unroll
            for (int j = 0; j < 4; j++) S[i][j] = 0.f;

#pragma unroll
        for (int kc = 0; kc < 12; kc++) {
            uint32_t qh[4], ql[4], kh[2][4], kl[2][4];
            uint32_t qoff = (uint32_t)((wid * 16 + a_row) * 200 + kc * 16 + a_k) * 2;
            ldsm4(qh, sQh + qoff);
            ldsm4(ql, sQl + qoff);
#pragma unroll
            for (int np = 0; np < 2; np++) {
                uint32_t koff = (uint32_t)((np * 16 + b_r + b_n) * 200 + kc * 16 + b_k) * 2;
                ldsm4(kh[np], sKh + koff);
                ldsm4(kl[np], sKl + koff);
            }
#pragma unroll
            for (int nf = 0; nf < 4; nf++) {
                const uint32_t* bhf = &kh[nf >> 1][(nf & 1) * 2];
                const uint32_t* blf = &kl[nf >> 1][(nf & 1) * 2];
                mma_bf16(S[nf], qh, bhf);
                mma_bf16(S[nf], qh, blf);
                mma_bf16(S[nf], ql, bhf);
            }
        }

        // ---- online softmax (rows g / g+8 per thread) ----
        float mx0 = fmaxf(fmaxf(S[0][0], S[0][1]), fmaxf(S[1][0], S[1][1]));
        mx0 = fmaxf(mx0, fmaxf(fmaxf(S[2][0], S[2][1]), fmaxf(S[3][0], S[3][1])));
        float mx1 = fmaxf(fmaxf(S[0][2], S[0][3]), fmaxf(S[1][2], S[1][3]));
        mx1 = fmaxf(mx1, fmaxf(fmaxf(S[2][2], S[2][3]), fmaxf(S[3][2], S[3][3])));
        mx0 = fmaxf(mx0, __shfl_xor_sync(0xffffffffu, mx0, 1));
        mx0 = fmaxf(mx0, __shfl_xor_sync(0xffffffffu, mx0, 2));
        mx1 = fmaxf(mx1, __shfl_xor_sync(0xffffffffu, mx1, 1));
        mx1 = fmaxf(mx1, __shfl_xor_sync(0xffffffffu, mx1, 2));
        float mn0 = fmaxf(m_lo, mx0), mn1 = fmaxf(m_hi, mx1);
        float a0 = __expf(m_lo - mn0), a1 = __expf(m_hi - mn1);
        m_lo = mn0; m_hi = mn1;

        float s0 = 0.f, s1 = 0.f;
#pragma unroll
        for (int nf = 0; nf < 4; nf++) {
            S[nf][0] = __expf(S[nf][0] - m_lo);
            S[nf][1] = __expf(S[nf][1] - m_lo);
            S[nf][2] = __expf(S[nf][2] - m_hi);
            S[nf][3] = __expf(S[nf][3] - m_hi);
            s0 += S[nf][0] + S[nf][1];
            s1 += S[nf][2] + S[nf][3];
        }
        s0 += __shfl_xor_sync(0xffffffffu, s0, 1);
        s0 += __shfl_xor_sync(0xffffffffu, s0, 2);
        s1 += __shfl_xor_sync(0xffffffffu, s1, 1);
        s1 += __shfl_xor_sync(0xffffffffu, s1, 2);
        l_lo = l_lo * a0 + s0;
        l_hi = l_hi * a1 + s1;

        if (__ballot_sync(0xffffffffu, (a0 != 1.f) || (a1 != 1.f))) {
#pragma unroll
            for (int nf = 0; nf < 24; nf++) {
                O[nf][0] *= a0; O[nf][1] *= a0;
                O[nf][2] *= a1; O[nf][3] *= a1;
            }
        }

        // ---- O += P V, 3 chains; P hi/lo split in registers ----
#pragma unroll
        for (int kc2 = 0; kc2 < 2; kc2++) {
            uint32_t ah[4], al[4];
#pragma unroll
            for (int r = 0; r < 4; r++) {
                const int f = 2 * kc2 + (r >> 1);
                const int c0 = (r & 1) * 2;
                __nv_bfloat16 h0, h1, e0, e1;
                split_bf16(S[f][c0], h0, e0);
                split_bf16(S[f][c0 + 1], h1, e1);
                ah[r] = pack2(h0, h1);
                al[r] = pack2(e0, e1);
            }
#pragma unroll
            for (int nb = 0; nb < 12; nb++) {
                uint32_t vh[4], vl[4];
                uint32_t voff = (uint32_t)((kc2 * 16 + a_row) * 200 + nb * 16 + a_k) * 2;
                ldsm4t(vh, sVh + voff);
                ldsm4t(vl, sVl + voff);
                mma_bf16(O[2 * nb],     ah, &vh[0]);
                mma_bf16(O[2 * nb],     ah, &vl[0]);
                mma_bf16(O[2 * nb],     al, &vh[0]);
                mma_bf16(O[2 * nb + 1], ah, &vh[2]);
                mma_bf16(O[2 * nb + 1], ah, &vl[2]);
                mma_bf16(O[2 * nb + 1], al, &vh[2]);
            }
        }

        __syncthreads();
        if (t + 2 < NKT) {
            uint32_t nb2 = sStage + (t & 1) * STAGE_AB;   // buf (t+2)&1 == t&1
#pragma unroll
            for (int j = 0; j < 12; j++) {
                int i = tid + j * 256;
                int tz = i / 768, idx = i % 768;
                int r = idx / 24, cc = (idx % 24) * 8;
                cpasync16(nb2 + tz * KV_TILE_B + (uint32_t)(r * 400 + cc * 2),
                          kvsrc[tz] + (size_t)((t + 2) * 32 + r) * DMODEL + cc);
            }
        }
        CP_COMMIT();
    }

    // ---- normalize + write ctx (hi,lo) ----
    const float i0 = 1.f / l_lo, i1 = 1.f / l_hi;
    const int row = qtile * 128 + wid * 16 + (lane >> 2);
    const int colb = h * DHEAD + (lane & 3) * 2;
#pragma unroll
    for (int nf = 0; nf < 24; nf++) {
        const int col = colb + nf * 8;
        float f0 = O[nf][0] * i0, f1 = O[nf][1] * i0;
        float f2 = O[nf][2] * i1, f3 = O[nf][3] * i1;
        __nv_bfloat16 h0, h1, h2, h3, e0, e1, e2, e3;
        split_bf16(f0, h0, e0); split_bf16(f1, h1, e1);
        split_bf16(f2, h2, e2); split_bf16(f3, h3, e3);
        size_t p0 = ((size_t)b * LSEQ + row) * DMODEL + col;
        size_t p1 = ((size_t)b * LSEQ + row + 8) * DMODEL + col;
        *(__nv_bfloat162*)(g_Chi + p0) = __halves2bfloat162(h0, h1);
        *(__nv_bfloat162*)(g_Clo + p0) = __halves2bfloat162(e0, e1);
        *(__nv_bfloat162*)(g_Chi + p1) = __halves2bfloat162(h2, h3);
        *(__nv_bfloat162*)(g_Clo + p1) = __halves2bfloat162(e2, e3);
    }
}

// ---------------------------------------------------------------------------
// Launch
// ---------------------------------------------------------------------------
extern "C" void kernel_launch(void* const* d_in, const int* in_sizes, int n_in,
                              void* d_out, int out_size) {
    const float* samples = (const float*)d_in[0];
    const float* Wq = (const float*)d_in[1];
    const float* bq = (const float*)d_in[2];
    const float* Wk = (const float*)d_in[3];
    const float* bk = (const float*)d_in[4];
    const float* Wv = (const float*)d_in[5];
    const float* bv = (const float*)d_in[6];
    const float* Wo = (const float*)d_in[7];
    const float* bo = (const float*)d_in[8];

    float* bqkv;
    __nv_bfloat16 *Ahi, *Alo, *Wqh, *Wql, *Woh, *Wol, *Chi, *Clo;
    __nv_bfloat16 *Qhp, *Qlp, *Khp, *Klp, *Vhp, *Vlp;
    cudaGetSymbolAddress((void**)&bqkv, g_bqkv);
    cudaGetSymbolAddress((void**)&Ahi,  g_Ahi);
    cudaGetSymbolAddress((void**)&Alo,  g_Alo);
    cudaGetSymbolAddress((void**)&Wqh,  g_Wqkv_hi);
    cudaGetSymbolAddress((void**)&Wql,  g_Wqkv_lo);
    cudaGetSymbolAddress((void**)&Woh,  g_Wo_hi);
    cudaGetSymbolAddress((void**)&Wol,  g_Wo_lo);
    cudaGetSymbolAddress((void**)&Chi,  g_Chi);
    cudaGetSymbolAddress((void**)&Clo,  g_Clo);
    cudaGetSymbolAddress((void**)&Qhp,  g_Qh);
    cudaGetSymbolAddress((void**)&Qlp,  g_Ql);
    cudaGetSymbolAddress((void**)&Khp,  g_Kh);
    cudaGetSymbolAddress((void**)&Klp,  g_Kl);
    cudaGetSymbolAddress((void**)&Vhp,  g_Vh);
    cudaGetSymbolAddress((void**)&Vlp,  g_Vl);

    {
        int n4 = MROWS * DIN / 4;
        conv_samples<<<(n4 + 255) / 256, 256>>>((const float4*)samples, n4);
        int nw = NQKV * DIN;
        conv_wqkv<<<(nw + 255) / 256, 256>>>(Wq, Wk, Wv, bq, bk, bv);
        int no = DMODEL * DMODEL;
        conv_wo<<<(no + 255) / 256, 256>>>(Wo);
    }

    cudaFuncSetAttribute(gemm_hilo<true>,  cudaFuncAttributeMaxDynamicSharedMemorySize, GEMM_SMEM);
    cudaFuncSetAttribute(gemm_hilo<false>, cudaFuncAttributeMaxDynamicSharedMemorySize, GEMM_SMEM);
    cudaFuncSetAttribute(attn_mma, cudaFuncAttributeMaxDynamicSharedMemorySize, ATTN_SMEM);

    // Fused QKV projection -> (hi,lo) bf16 Q,K,V
    gemm_hilo<true><<<dim3(NQKV / 128, MROWS / 128), 256, GEMM_SMEM>>>(
        Ahi, Alo, Wqh, Wql, bqkv, nullptr,
        Qhp, Qlp, Khp, Klp, Vhp, Vlp, DIN, DMODEL, DMODEL / 128);

    // Tensor-core flash attention
    attn_mma<<<dim3(LSEQ / 128, BATCH * NHEADS), 256, ATTN_SMEM>>>(
        Qhp, Qlp, Khp, Klp, Vhp, Vlp);

    // Output projection -> fp32 d_out
    gemm_hilo<false><<<dim3(DMODEL / 128, MROWS / 128), 256, GEMM_SMEM>>>(
        Chi, Clo, Woh, Wol, bo, (float*)d_out,
        nullptr, nullptr, nullptr, nullptr, nullptr, nullptr,
        DMODEL, DMODEL, DMODEL / 128);
}

// round 10
// speedup vs baseline: 3.2271x; 1.1057x over previous
#include <cuda_runtime.h>
#include <cuda_bf16.h>
#include <cstdint>

// Problem dims (fixed by the reference)
#define BATCH   8
#define LSEQ    2048
#define DMODEL  768
#define DIN     1536
#define NHEADS  4
#define DHEAD   192
#define MROWS   (BATCH * LSEQ)   // 16384
#define NQKV    (3 * DMODEL)     // 2304

// ---------------------------------------------------------------------------
// Scratch (allocation-free rule: __device__ globals)
// ---------------------------------------------------------------------------
__device__ __nv_bfloat16 g_Ahi[MROWS * DIN];
__device__ __nv_bfloat16 g_Alo[MROWS * DIN];
__device__ __nv_bfloat16 g_Wqkv_hi[NQKV * DIN];    // [n][k] K-major
__device__ __nv_bfloat16 g_Wqkv_lo[NQKV * DIN];
__device__ __nv_bfloat16 g_Wo_hi[DMODEL * DMODEL]; // [n][k] K-major
__device__ __nv_bfloat16 g_Wo_lo[DMODEL * DMODEL];
__device__ float g_bqkv[NQKV];
__device__ __nv_bfloat16 g_Qh[MROWS * DMODEL];
__device__ __nv_bfloat16 g_Ql[MROWS * DMODEL];
__device__ __nv_bfloat16 g_Kh[MROWS * DMODEL];
__device__ __nv_bfloat16 g_Kl[MROWS * DMODEL];
__device__ __nv_bfloat16 g_Vh[MROWS * DMODEL];
__device__ __nv_bfloat16 g_Vl[MROWS * DMODEL];
__device__ __nv_bfloat16 g_Chi[MROWS * DMODEL];
__device__ __nv_bfloat16 g_Clo[MROWS * DMODEL];

// ---------------------------------------------------------------------------
// Base-ISA helpers
// ---------------------------------------------------------------------------
__device__ __forceinline__ uint32_t smem_to_u32(const void* p) {
    uint32_t a;
    asm("{ .reg .u64 t; cvta.to.shared.u64 t, %1; cvt.u32.u64 %0, t; }"
        : "=r"(a) : "l"(p));
    return a;
}
__device__ __forceinline__ void ldsm4(uint32_t* r, uint32_t addr) {
    asm volatile("ldmatrix.sync.aligned.m8n8.x4.shared.b16 {%0,%1,%2,%3}, [%4];"
                 : "=r"(r[0]), "=r"(r[1]), "=r"(r[2]), "=r"(r[3]) : "r"(addr));
}
__device__ __forceinline__ void ldsm4t(uint32_t* r, uint32_t addr) {
    asm volatile("ldmatrix.sync.aligned.m8n8.x4.trans.shared.b16 {%0,%1,%2,%3}, [%4];"
                 : "=r"(r[0]), "=r"(r[1]), "=r"(r[2]), "=r"(r[3]) : "r"(addr));
}
__device__ __forceinline__ void mma_bf16(float* c, const uint32_t* a, const uint32_t* b) {
    asm volatile(
        "mma.sync.aligned.m16n8k16.row.col.f32.bf16.bf16.f32 "
        "{%0,%1,%2,%3}, {%4,%5,%6,%7}, {%8,%9}, {%0,%1,%2,%3};"
        : "+f"(c[0]), "+f"(c[1]), "+f"(c[2]), "+f"(c[3])
        : "r"(a[0]), "r"(a[1]), "r"(a[2]), "r"(a[3]), "r"(b[0]), "r"(b[1]));
}
__device__ __forceinline__ void cpasync16(uint32_t saddr, const void* g) {
    asm volatile("cp.async.cg.shared.global [%0], [%1], 16;" :: "r"(saddr), "l"(g));
}
#define CP_COMMIT() asm volatile("cp.async.commit_group;" ::: "memory")
#define CP_WAIT1()  asm volatile("cp.async.wait_group 1;" ::: "memory")

__device__ __forceinline__ void split_bf16(float v, __nv_bfloat16& h, __nv_bfloat16& l) {
    h = __float2bfloat16(v);
    l = __float2bfloat16(v - __bfloat162float(h));
}
__device__ __forceinline__ uint32_t pack2(__nv_bfloat16 a, __nv_bfloat16 b) {
    __nv_bfloat162 t = __halves2bfloat162(a, b);
    return *(uint32_t*)&t;
}

// ---------------------------------------------------------------------------
// Preprocessing (all coalesced)
// ---------------------------------------------------------------------------
__global__ void conv_samples(const float4* __restrict__ src, int n4) {
    int i = blockIdx.x * 256 + threadIdx.x;
    if (i >= n4) return;
    float4 v = src[i];
    __nv_bfloat16 h0, h1, h2, h3, l0, l1, l2, l3;
    split_bf16(v.x, h0, l0); split_bf16(v.y, h1, l1);
    split_bf16(v.z, h2, l2); split_bf16(v.w, h3, l3);
    *(__nv_bfloat162*)(g_Ahi + 4 * (size_t)i)     = __halves2bfloat162(h0, h1);
    *(__nv_bfloat162*)(g_Ahi + 4 * (size_t)i + 2) = __halves2bfloat162(h2, h3);
    *(__nv_bfloat162*)(g_Alo + 4 * (size_t)i)     = __halves2bfloat162(l0, l1);
    *(__nv_bfloat162*)(g_Alo + 4 * (size_t)i + 2) = __halves2bfloat162(l2, l3);
}

// Tile-transpose W[K][N] -> out[n][k] hi/lo, coalesced both directions.
__global__ void conv_wqkv_t(const float* __restrict__ Wq, const float* __restrict__ Wk,
                            const float* __restrict__ Wv) {
    __shared__ float t[32][33];
    const int mat = blockIdx.z;
    const float* W = (mat == 0) ? Wq : (mat == 1) ? Wk : Wv;
    const int n0 = blockIdx.x * 32, k0 = blockIdx.y * 32;
    const int tx = threadIdx.x, ty = threadIdx.y;
#pragma unroll
    for (int r = 0; r < 32; r += 8)
        t[ty + r][tx] = W[(size_t)(k0 + ty + r) * DMODEL + n0 + tx];
    __syncthreads();
#pragma unroll
    for (int r = 0; r < 32; r += 8) {
        float v = t[tx][ty + r];           // = W[k0+tx][n0+ty+r]
        __nv_bfloat16 h, l; split_bf16(v, h, l);
        size_t o = (size_t)(mat * DMODEL + n0 + ty + r) * DIN + k0 + tx;
        g_Wqkv_hi[o] = h; g_Wqkv_lo[o] = l;
    }
}

__global__ void conv_wo_t(const float* __restrict__ Wo) {
    __shared__ float t[32][33];
    const int n0 = blockIdx.x * 32, k0 = blockIdx.y * 32;
    const int tx = threadIdx.x, ty = threadIdx.y;
#pragma unroll
    for (int r = 0; r < 32; r += 8)
        t[ty + r][tx] = Wo[(size_t)(k0 + ty + r) * DMODEL + n0 + tx];
    __syncthreads();
#pragma unroll
    for (int r = 0; r < 32; r += 8) {
        float v = t[tx][ty + r];
        __nv_bfloat16 h, l; split_bf16(v, h, l);
        size_t o = (size_t)(n0 + ty + r) * DMODEL + k0 + tx;
        g_Wo_hi[o] = h; g_Wo_lo[o] = l;
    }
}

__global__ void conv_bias(const float* __restrict__ bq, const float* __restrict__ bk,
                          const float* __restrict__ bv) {
    int i = blockIdx.x * 256 + threadIdx.x;
    if (i < NQKV)
        g_bqkv[i] = (i < DMODEL) ? bq[i] : (i < 2 * DMODEL) ? bk[i - DMODEL] : bv[i - 2 * DMODEL];
}

// ---------------------------------------------------------------------------
// mma.sync split-bf16 GEMM: C[M,N] = A[M,K] @ W[K,N] + bias
// 2-stage cp.async pipeline (80KB smem), 2 CTAs/SM. B frags resident,
// A frags streamed per-mf to stay under 128 regs.
// ---------------------------------------------------------------------------
#define TROW    40
#define TILE_B  (128 * TROW * 2)
#define STAGE_B (4 * TILE_B)
#define NSTAGE  2
#define GEMM_SMEM (NSTAGE * STAGE_B)     // 81920

__device__ __forceinline__ void issue_stage(
    uint32_t sbase, const __nv_bfloat16* __restrict__ Ah,
    const __nv_bfloat16* __restrict__ Al, const __nv_bfloat16* __restrict__ Bh,
    const __nv_bfloat16* __restrict__ Bl, int row0, int n0g, int k0, int K, int tid) {
    const __nv_bfloat16* srcs[4] = {Ah, Al, Bh, Bl};
#pragma unroll
    for (int t = 0; t < 8; t++) {
        int c    = tid + t * 256;
        int tile = c >> 9;
        int idx  = c & 511;
        int row  = idx >> 2;
        int kc   = (idx & 3) * 8;
        int grow = ((tile < 2) ? row0 : n0g) + row;
        const __nv_bfloat16* g = srcs[tile] + (size_t)grow * K + k0 + kc;
        uint32_t saddr = sbase + tile * TILE_B + (uint32_t)(row * TROW + kc) * 2;
        cpasync16(saddr, g);
    }
}

template <bool BF16OUT>
__global__ __launch_bounds__(256, 2)
void gemm_hilo(const __nv_bfloat16* __restrict__ Ah, const __nv_bfloat16* __restrict__ Al,
               const __nv_bfloat16* __restrict__ Bh, const __nv_bfloat16* __restrict__ Bl,
               const float* __restrict__ bias, float* outF,
               __nv_bfloat16* o0h, __nv_bfloat16* o0l,
               __nv_bfloat16* o1h, __nv_bfloat16* o1l,
               __nv_bfloat16* o2h, __nv_bfloat16* o2l,
               int K, int Nout, int ntpm) {
    extern __shared__ char smem[];
    const uint32_t smem_u = smem_to_u32(smem);
    const int tid  = threadIdx.x;
    const int lane = tid & 31;
    const int wid  = tid >> 5;
    const int bx = blockIdx.x, by = blockIdx.y;

    const int mat = bx / ntpm;
    const int row0 = by * 128;
    const int n0g  = bx * 128;
    const int n0   = (bx % ntpm) * 128;

    const int wm = wid >> 2;
    const int wn = wid & 3;
    const int ns = K / 32;

    issue_stage(smem_u, Ah, Al, Bh, Bl, row0, n0g, 0, K, tid);
    CP_COMMIT();
    issue_stage(smem_u + STAGE_B, Ah, Al, Bh, Bl, row0, n0g, 32, K, tid);
    CP_COMMIT();

    float c[4][4][4];
#pragma unroll
    for (int i = 0; i < 4; i++)
#pragma unroll
        for (int j = 0; j < 4; j++)
#pragma unroll
            for (int q = 0; q < 4; q++) c[i][j][q] = 0.f;

    const int a_row = lane & 15;
    const int a_kad = (lane >> 4) * 8;
    const int b_r   = lane & 7;
    const int b_q   = lane >> 3;
    const int b_nad = (b_q >> 1) * 8;
    const int b_kad = (b_q & 1) * 8;

    for (int s = 0; s < ns; s++) {
        CP_WAIT1();
        __syncthreads();

        const uint32_t sb  = smem_u + (s & 1) * STAGE_B;
        const uint32_t sAh = sb;
        const uint32_t sAl = sb + TILE_B;
        const uint32_t sBh = sb + 2 * TILE_B;
        const uint32_t sBl = sb + 3 * TILE_B;

#pragma unroll
        for (int ks = 0; ks < 2; ks++) {
            uint32_t bh[2][4], bl[2][4];
#pragma unroll
            for (int np = 0; np < 2; np++) {
                uint32_t off = ((uint32_t)((wn * 32 + np * 16 + b_r + b_nad) * TROW
                                           + ks * 16 + b_kad)) * 2;
                ldsm4(bh[np], sBh + off);
                ldsm4(bl[np], sBl + off);
            }
#pragma unroll
            for (int mf = 0; mf < 4; mf++) {
                uint32_t ah[4], al[4];
                uint32_t off = ((uint32_t)((wm * 64 + mf * 16 + a_row) * TROW
                                           + ks * 16 + a_kad)) * 2;
                ldsm4(ah, sAh + off);
                ldsm4(al, sAl + off);
#pragma unroll
                for (int nf = 0; nf < 4; nf++) {
                    const int np = nf >> 1, bo = (nf & 1) * 2;
                    mma_bf16(c[mf][nf], ah, &bh[np][bo]);
                    mma_bf16(c[mf][nf], ah, &bl[np][bo]);
                    mma_bf16(c[mf][nf], al, &bh[np][bo]);
                }
            }
        }
        __syncthreads();
        if (s + 2 < ns)
            issue_stage(sb, Ah, Al, Bh, Bl, row0, n0g, (s + 2) * 32, K, tid);
        CP_COMMIT();
    }

    const int g  = lane >> 2;
    const int tg = lane & 3;
#pragma unroll
    for (int nf = 0; nf < 4; nf++) {
        const int colL = wn * 32 + nf * 8 + 2 * tg;
        const float b0 = bias[n0g + colL];
        const float b1 = bias[n0g + colL + 1];
#pragma unroll
        for (int mf = 0; mf < 4; mf++) {
            const int row = row0 + wm * 64 + mf * 16 + g;
            float f0 = c[mf][nf][0] + b0, f1 = c[mf][nf][1] + b1;
            float f2 = c[mf][nf][2] + b0, f3 = c[mf][nf][3] + b1;
            if (BF16OUT) {
                __nv_bfloat16* oh = (mat == 0) ? o0h : (mat == 1) ? o1h : o2h;
                __nv_bfloat16* ol = (mat == 0) ? o0l : (mat == 1) ? o1l : o2l;
                __nv_bfloat16 h0, h1, h2, h3, e0, e1, e2, e3;
                split_bf16(f0, h0, e0); split_bf16(f1, h1, e1);
                split_bf16(f2, h2, e2); split_bf16(f3, h3, e3);
                size_t p0 = (size_t)row * Nout + n0 + colL;
                size_t p1 = (size_t)(row + 8) * Nout + n0 + colL;
                *(__nv_bfloat162*)(oh + p0) = __halves2bfloat162(h0, h1);
                *(__nv_bfloat162*)(ol + p0) = __halves2bfloat162(e0, e1);
                *(__nv_bfloat162*)(oh + p1) = __halves2bfloat162(h2, h3);
                *(__nv_bfloat162*)(ol + p1) = __halves2bfloat162(e2, e3);
            } else {
                *(float2*)(outF + (size_t)row * Nout + n0 + colL)       = {f0, f1};
                *(float2*)(outF + (size_t)(row + 8) * Nout + n0 + colL) = {f2, f3};
            }
        }
    }
}

// ---------------------------------------------------------------------------
// Tensor-core flash attention (hi/lo bf16, fp32 accum, online softmax).
// ---------------------------------------------------------------------------
#define AROW      200
#define AQ_BYTES  (128 * AROW * 2)
#define KV_TILE_B (32 * AROW * 2)
#define STAGE_AB  (4 * KV_TILE_B)
#define ATTN_SMEM (2 * AQ_BYTES + 2 * STAGE_AB)
#define NKT       (LSEQ / 32)

__global__ __launch_bounds__(256, 1)
void attn_mma(const __nv_bfloat16* __restrict__ Qh, const __nv_bfloat16* __restrict__ Ql,
              const __nv_bfloat16* __restrict__ Kh, const __nv_bfloat16* __restrict__ Kl,
              const __nv_bfloat16* __restrict__ Vh, const __nv_bfloat16* __restrict__ Vl) {
    extern __shared__ char sm[];
    const uint32_t su = smem_to_u32(sm);
    const uint32_t sQh = su, sQl = su + AQ_BYTES;
    const uint32_t sStage = su + 2 * AQ_BYTES;

    const int tid = threadIdx.x, wid = tid >> 5, lane = tid & 31;
    const int qtile = blockIdx.x, bh = blockIdx.y;
    const int b = bh / NHEADS, h = bh % NHEADS;
    const size_t gbase = (size_t)b * LSEQ * DMODEL + h * DHEAD;

    const __nv_bfloat16* Qgh = Qh + gbase + (size_t)qtile * 128 * DMODEL;
    const __nv_bfloat16* Qgl = Ql + gbase + (size_t)qtile * 128 * DMODEL;
    const __nv_bfloat16* Kgh = Kh + gbase;
    const __nv_bfloat16* Kgl = Kl + gbase;
    const __nv_bfloat16* Vgh = Vh + gbase;
    const __nv_bfloat16* Vgl = Vl + gbase;

    for (int i = tid; i < 2 * 3072; i += 256) {
        int tz = i / 3072, idx = i % 3072;
        int r = idx / 24, cc = (idx % 24) * 8;
        const __nv_bfloat16* src = (tz ? Qgl : Qgh) + (size_t)r * DMODEL + cc;
        uint4 v = *(const uint4*)src;
        *(uint4*)(sm + (tz ? AQ_BYTES : 0) + r * 400 + cc * 2) = v;
    }

    const __nv_bfloat16* kvsrc[4] = {Kgh, Kgl, Vgh, Vgl};
#pragma unroll
    for (int st = 0; st < 2; st++) {
        uint32_t sb = sStage + st * STAGE_AB;
#pragma unroll
        for (int j = 0; j < 12; j++) {
            int i = tid + j * 256;
            int tz = i / 768, idx = i % 768;
            int r = idx / 24, cc = (idx % 24) * 8;
            cpasync16(sb + tz * KV_TILE_B + (uint32_t)(r * 400 + cc * 2),
                      kvsrc[tz] + (size_t)(st * 32 + r) * DMODEL + cc);
        }
        CP_COMMIT();
    }
    __syncthreads();

    const int a_row = lane & 15;
    const int a_k   = (lane >> 4) * 8;
    const int b_r   = lane & 7;
    const int b_q   = lane >> 3;
    const int b_n   = (b_q >> 1) * 8;
    const int b_k   = (b_q & 1) * 8;

    float O[24][4];
#pragma unroll
    for (int i = 0; i < 24; i++)
#pragma unroll
        for (int j = 0; j < 4; j++) O[i][j] = 0.f;
    float m_lo = -1e30f, m_hi = -1e30f, l_lo = 0.f, l_hi = 0.f;

    for (int t = 0; t < NKT; t++) {
        CP_WAIT1();
        __syncthreads();
        const uint32_t sb  = sStage + (t & 1) * STAGE_AB;
        const uint32_t sKh = sb, sKl = sb + KV_TILE_B;
        const uint32_t sVh = sb + 2 * KV_TILE_B, sVl = sb + 3 * KV_TILE_B;

        float S[4][4];
#pragma unroll
        for (int i = 0; i < 4; i++)
#pragma unroll
            for (int j = 0; j < 4; j++) S[i][j] = 0.f;

#pragma unroll
        for (int kc = 0; kc < 12; kc++) {
            uint32_t qh[4], ql[4], kh[2][4], kl[2][4];
            uint32_t qoff = (uint32_t)((wid * 16 + a_row) * 200 + kc * 16 + a_k) * 2;
            ldsm4(qh, sQh + qoff);
            ldsm4(ql, sQl + qoff);
#pragma unroll
            for (int np = 0; np < 2; np++) {
                uint32_t koff = (uint32_t)((np * 16 + b_r + b_n) * 200 + kc * 16 + b_k) * 2;
                ldsm4(kh[np], sKh + koff);
                ldsm4(kl[np], sKl + koff);
            }
#pragma unroll
            for (int nf = 0; nf < 4; nf++) {
                const uint32_t* bhf = &kh[nf >> 1][(nf & 1) * 2];
                const uint32_t* blf = &kl[nf >> 1][(nf & 1) * 2];
                mma_bf16(S[nf], qh, bhf);
                mma_bf16(S[nf], qh, blf);
                mma_bf16(S[nf], ql, bhf);
            }
        }

        float mx0 = fmaxf(fmaxf(S[0][0], S[0][1]), fmaxf(S[1][0], S[1][1]));
        mx0 = fmaxf(mx0, fmaxf(fmaxf(S[2][0], S[2][1]), fmaxf(S[3][0], S[3][1])));
        float mx1 = fmaxf(fmaxf(S[0][2], S[0][3]), fmaxf(S[1][2], S[1][3]));
        mx1 = fmaxf(mx1, fmaxf(fmaxf(S[2][2], S[2][3]), fmaxf(S[3][2], S[3][3])));
        mx0 = fmaxf(mx0, __shfl_xor_sync(0xffffffffu, mx0, 1));
        mx0 = fmaxf(mx0, __shfl_xor_sync(0xffffffffu, mx0, 2));
        mx1 = fmaxf(mx1, __shfl_xor_sync(0xffffffffu, mx1, 1));
        mx1 = fmaxf(mx1, __shfl_xor_sync(0xffffffffu, mx1, 2));
        float mn0 = fmaxf(m_lo, mx0), mn1 = fmaxf(m_hi, mx1);
        float a0 = __expf(m_lo - mn0), a1 = __expf(m_hi - mn1);
        m_lo = mn0; m_hi = mn1;

        float s0 = 0.f, s1 = 0.f;
#pragma unroll
        for (int nf = 0; nf < 4; nf++) {
            S[nf][0] = __expf(S[nf][0] - m_lo);
            S[nf][1] = __expf(S[nf][1] - m_lo);
            S[nf][2] = __expf(S[nf][2] - m_hi);
            S[nf][3] = __expf(S[nf][3] - m_hi);
            s0 += S[nf][0] + S[nf][1];
            s1 += S[nf][2] + S[nf][3];
        }
        s0 += __shfl_xor_sync(0xffffffffu, s0, 1);
        s0 += __shfl_xor_sync(0xffffffffu, s0, 2);
        s1 += __shfl_xor_sync(0xffffffffu, s1, 1);
        s1 += __shfl_xor_sync(0xffffffffu, s1, 2);
        l_lo = l_lo * a0 + s0;
        l_hi = l_hi * a1 + s1;

        if (__ballot_sync(0xffffffffu, (a0 != 1.f) || (a1 != 1.f))) {
#pragma unroll
            for (int nf = 0; nf < 24; nf++) {
                O[nf][0] *= a0; O[nf][1] *= a0;
                O[nf][2] *= a1; O[nf][3] *= a1;
            }
        }

#pragma unroll
        for (int kc2 = 0; kc2 < 2; kc2++) {
            uint32_t ah[4], al[4];
#pragma unroll
            for (int r = 0; r < 4; r++) {
                const int f = 2 * kc2 + (r >> 1);
                const int c0 = (r & 1) * 2;
                __nv_bfloat16 h0, h1, e0, e1;
                split_bf16(S[f][c0], h0, e0);
                split_bf16(S[f][c0 + 1], h1, e1);
                ah[r] = pack2(h0, h1);
                al[r] = pack2(e0, e1);
            }
#pragma unroll
            for (int nb = 0; nb < 12; nb++) {
                uint32_t vh[4], vl[4];
                uint32_t voff = (uint32_t)((kc2 * 16 + a_row) * 200 + nb * 16 + a_k) * 2;
                ldsm4t(vh, sVh + voff);
                ldsm4t(vl, sVl + voff);
                mma_bf16(O[2 * nb],     ah, &vh[0]);
                mma_bf16(O[2 * nb],     ah, &vl[0]);
                mma_bf16(O[2 * nb],     al, &vh[0]);
                mma_bf16(O[2 * nb + 1], ah, &vh[2]);
                mma_bf16(O[2 * nb + 1], ah, &vl[2]);
                mma_bf16(O[2 * nb + 1], al, &vh[2]);
            }
        }

        __syncthreads();
        if (t + 2 < NKT) {
            uint32_t nb2 = sStage + (t & 1) * STAGE_AB;
#pragma unroll
            for (int j = 0; j < 12; j++) {
                int i = tid + j * 256;
                int tz = i / 768, idx = i % 768;
                int r = idx / 24, cc = (idx % 24) * 8;
                cpasync16(nb2 + tz * KV_TILE_B + (uint32_t)(r * 400 + cc * 2),
                          kvsrc[tz] + (size_t)((t + 2) * 32 + r) * DMODEL + cc);
            }
        }
        CP_COMMIT();
    }

    const float i0 = 1.f / l_lo, i1 = 1.f / l_hi;
    const int row = qtile * 128 + wid * 16 + (lane >> 2);
    const int colb = h * DHEAD + (lane & 3) * 2;
#pragma unroll
    for (int nf = 0; nf < 24; nf++) {
        const int col = colb + nf * 8;
        float f0 = O[nf][0] * i0, f1 = O[nf][1] * i0;
        float f2 = O[nf][2] * i1, f3 = O[nf][3] * i1;
        __nv_bfloat16 h0, h1, h2, h3, e0, e1, e2, e3;
        split_bf16(f0, h0, e0); split_bf16(f1, h1, e1);
        split_bf16(f2, h2, e2); split_bf16(f3, h3, e3);
        size_t p0 = ((size_t)b * LSEQ + row) * DMODEL + col;
        size_t p1 = ((size_t)b * LSEQ + row + 8) * DMODEL + col;
        *(__nv_bfloat162*)(g_Chi + p0) = __halves2bfloat162(h0, h1);
        *(__nv_bfloat162*)(g_Clo + p0) = __halves2bfloat162(e0, e1);
        *(__nv_bfloat162*)(g_Chi + p1) = __halves2bfloat162(h2, h3);
        *(__nv_bfloat162*)(g_Clo + p1) = __halves2bfloat162(e2, e3);
    }
}

// ---------------------------------------------------------------------------
// Launch
// ---------------------------------------------------------------------------
extern "C" void kernel_launch(void* const* d_in, const int* in_sizes, int n_in,
                              void* d_out, int out_size) {
    const float* samples = (const float*)d_in[0];
    const float* Wq = (const float*)d_in[1];
    const float* bq = (const float*)d_in[2];
    const float* Wk = (const float*)d_in[3];
    const float* bk = (const float*)d_in[4];
    const float* Wv = (const float*)d_in[5];
    const float* bv = (const float*)d_in[6];
    const float* Wo = (const float*)d_in[7];
    const float* bo = (const float*)d_in[8];

    float* bqkv;
    __nv_bfloat16 *Ahi, *Alo, *Wqh, *Wql, *Woh, *Wol, *Chi, *Clo;
    __nv_bfloat16 *Qhp, *Qlp, *Khp, *Klp, *Vhp, *Vlp;
    cudaGetSymbolAddress((void**)&bqkv, g_bqkv);
    cudaGetSymbolAddress((void**)&Ahi,  g_Ahi);
    cudaGetSymbolAddress((void**)&Alo,  g_Alo);
    cudaGetSymbolAddress((void**)&Wqh,  g_Wqkv_hi);
    cudaGetSymbolAddress((void**)&Wql,  g_Wqkv_lo);
    cudaGetSymbolAddress((void**)&Woh,  g_Wo_hi);
    cudaGetSymbolAddress((void**)&Wol,  g_Wo_lo);
    cudaGetSymbolAddress((void**)&Chi,  g_Chi);
    cudaGetSymbolAddress((void**)&Clo,  g_Clo);
    cudaGetSymbolAddress((void**)&Qhp,  g_Qh);
    cudaGetSymbolAddress((void**)&Qlp,  g_Ql);
    cudaGetSymbolAddress((void**)&Khp,  g_Kh);
    cudaGetSymbolAddress((void**)&Klp,  g_Kl);
    cudaGetSymbolAddress((void**)&Vhp,  g_Vh);
    cudaGetSymbolAddress((void**)&Vlp,  g_Vl);

    {
        int n4 = MROWS * DIN / 4;
        conv_samples<<<(n4 + 255) / 256, 256>>>((const float4*)samples, n4);
        conv_wqkv_t<<<dim3(DMODEL / 32, DIN / 32, 3), dim3(32, 8)>>>(Wq, Wk, Wv);
        conv_wo_t<<<dim3(DMODEL / 32, DMODEL / 32), dim3(32, 8)>>>(Wo);
        conv_bias<<<(NQKV + 255) / 256, 256>>>(bq, bk, bv);
    }

    cudaFuncSetAttribute(gemm_hilo<true>,  cudaFuncAttributeMaxDynamicSharedMemorySize, GEMM_SMEM);
    cudaFuncSetAttribute(gemm_hilo<false>, cudaFuncAttributeMaxDynamicSharedMemorySize, GEMM_SMEM);
    cudaFuncSetAttribute(attn_mma, cudaFuncAttributeMaxDynamicSharedMemorySize, ATTN_SMEM);

    // Fused QKV projection -> (hi,lo) bf16 Q,K,V
    gemm_hilo<true><<<dim3(NQKV / 128, MROWS / 128), 256, GEMM_SMEM>>>(
        Ahi, Alo, Wqh, Wql, bqkv, nullptr,
        Qhp, Qlp, Khp, Klp, Vhp, Vlp, DIN, DMODEL, DMODEL / 128);

    // Tensor-core flash attention
    attn_mma<<<dim3(LSEQ / 128, BATCH * NHEADS), 256, ATTN_SMEM>>>(
        Qhp, Qlp, Khp, Klp, Vhp, Vlp);

    // Output projection -> fp32 d_out
    gemm_hilo<false><<<dim3(DMODEL / 128, MROWS / 128), 256, GEMM_SMEM>>>(
        Chi, Clo, Woh, Wol, bo, (float*)d_out,
        nullptr, nullptr, nullptr, nullptr, nullptr, nullptr,
        DMODEL, DMODEL, DMODEL / 128);
}